// round 11
// baseline (speedup 1.0000x reference)
#include <cuda_runtime.h>
#include <cuda_bf16.h>
#include <cstdint>

// out[m,u] = ||x_m||^2 - 2*(x_m . w_u) + ||w_u||^2
// M = 524288, D = 64, U = 64. bf16 mma.sync m16n8k16 cross term.
// R9 skeleton (one-shot CTA / 256 rows, TMA bulk input, 2-tile amortized MMA)
// + NEW: output written via cp.async.bulk S2G (linear 2KB slots, bank-rotated
// staging) -> stores leave on the bulk engine, off the warp critical path.

#define DEPTH 64
#define UNITS 64
#define CHUNK_ROWS 128
#define CHUNK_BYTES (CHUNK_ROWS * DEPTH * 4)   // 32768

// dynamic smem layout
#define OFF_STAGE  0                    // 2 x 32768
#define OFF_BUF    65536                // 8 warps x 4096 (tile bufs / store slots)
#define OFF_FRAGB  98304                // 16*32*16 = 8192
#define OFF_W2     106496               // 256
#define OFF_X2     106752               // 8*32*4 = 1024
#define OFF_MBAR   107776               // 16
#define SMEM_TOTAL 107800

__device__ __forceinline__ uint32_t pack_bf16x2(float lo, float hi) {
    uint32_t r;
    asm("cvt.rn.bf16x2.f32 %0, %1, %2;" : "=r"(r) : "f"(hi), "f"(lo));
    return r;
}

__device__ __forceinline__ void mma_bf16(float c[4],
                                         uint32_t a0, uint32_t a1, uint32_t a2, uint32_t a3,
                                         uint32_t b0, uint32_t b1) {
    asm volatile(
        "mma.sync.aligned.m16n8k16.row.col.f32.bf16.bf16.f32 "
        "{%0,%1,%2,%3}, {%4,%5,%6,%7}, {%8,%9}, {%0,%1,%2,%3};"
        : "+f"(c[0]), "+f"(c[1]), "+f"(c[2]), "+f"(c[3])
        : "r"(a0), "r"(a1), "r"(a2), "r"(a3), "r"(b0), "r"(b1));
}

__device__ __forceinline__ void ldsm_x4(uint32_t r[4], uint32_t smem_addr) {
    asm volatile("ldmatrix.sync.aligned.m8n8.x4.shared.b16 {%0,%1,%2,%3}, [%4];"
                 : "=r"(r[0]), "=r"(r[1]), "=r"(r[2]), "=r"(r[3])
                 : "r"(smem_addr));
}

__device__ __forceinline__ uint32_t smem_u32(const void* p) {
    return (uint32_t)__cvta_generic_to_shared(p);
}

__device__ __forceinline__ void mbar_init(uint32_t mbar, uint32_t count) {
    asm volatile("mbarrier.init.shared.b64 [%0], %1;" :: "r"(mbar), "r"(count) : "memory");
}
__device__ __forceinline__ void mbar_expect_tx(uint32_t mbar, uint32_t bytes) {
    asm volatile("mbarrier.arrive.expect_tx.shared.b64 _, [%0], %1;"
                 :: "r"(mbar), "r"(bytes) : "memory");
}
__device__ __forceinline__ void bulk_copy_g2s(uint32_t dst, const void* src,
                                              uint32_t bytes, uint32_t mbar) {
    asm volatile(
        "cp.async.bulk.shared::cluster.global.mbarrier::complete_tx::bytes "
        "[%0], [%1], %2, [%3];"
        :: "r"(dst), "l"(src), "r"(bytes), "r"(mbar) : "memory");
}
__device__ __forceinline__ void bulk_copy_s2g(void* dst, uint32_t src_smem,
                                              uint32_t bytes) {
    asm volatile(
        "cp.async.bulk.global.shared::cta.bulk_group [%0], [%1], %2;"
        :: "l"(dst), "r"(src_smem), "r"(bytes) : "memory");
}
__device__ __forceinline__ void bulk_commit() {
    asm volatile("cp.async.bulk.commit_group;" ::: "memory");
}
template <int N>
__device__ __forceinline__ void bulk_wait_group() {
    asm volatile("cp.async.bulk.wait_group %0;" :: "n"(N) : "memory");
}
__device__ __forceinline__ void fence_proxy_async_() {
    asm volatile("fence.proxy.async;" ::: "memory");
}
__device__ __forceinline__ void mbar_wait(uint32_t mbar, uint32_t parity) {
    uint32_t done;
    asm volatile(
        "{\n\t.reg .pred p;\n\t"
        "mbarrier.try_wait.parity.acquire.cta.shared::cta.b64 p, [%1], %2;\n\t"
        "selp.b32 %0, 1, 0, p;\n\t}"
        : "=r"(done) : "r"(mbar), "r"(parity) : "memory");
    if (!done) {
        asm volatile(
            "{\n\t.reg .pred P1;\n\t"
            "WAIT_LOOP_%=:\n\t"
            "mbarrier.try_wait.parity.acquire.cta.shared::cta.b64 P1, [%0], %1, 0x989680;\n\t"
            "@P1 bra.uni WAIT_DONE_%=;\n\t"
            "bra.uni WAIT_LOOP_%=;\n\t"
            "WAIT_DONE_%=:\n\t}"
            :: "r"(mbar), "r"(parity) : "memory");
    }
}

__global__ __launch_bounds__(256, 2) void sqdist_kernel(
    const float* __restrict__ x, const float* __restrict__ w,
    float* __restrict__ out)
{
    extern __shared__ __align__(16) char smem[];
    float* stage = reinterpret_cast<float*>(smem + OFF_STAGE);
    uint4 (*fragB4)[32] = reinterpret_cast<uint4(*)[32]>(smem + OFF_FRAGB);
    float* w2_s  = reinterpret_cast<float*>(smem + OFF_W2);
    float* x2s   = reinterpret_cast<float*>(smem + OFF_X2);   // [8][32]
    const uint32_t mbar0 = smem_u32(smem + OFF_MBAR);
    const uint32_t mbar1 = mbar0 + 8;

    const int tid  = threadIdx.x;
    const int warp = tid >> 5;
    const int lane = tid & 31;

    const long ctarow = (long)blockIdx.x * 256;
    const float* xbase = x + ctarow * DEPTH;

    // ---- Issue both chunk loads FIRST (overlap with prologue).
    if (tid == 0) {
        mbar_init(mbar0, 1);
        mbar_init(mbar1, 1);
        mbar_expect_tx(mbar0, CHUNK_BYTES);
        bulk_copy_g2s(smem_u32(stage), xbase, CHUNK_BYTES, mbar0);
        mbar_expect_tx(mbar1, CHUNK_BYTES);
        bulk_copy_g2s(smem_u32(stage + 8192), xbase + CHUNK_ROWS * DEPTH,
                      CHUNK_BYTES, mbar1);
    }

    // ---- Prologue: w2 (fp32)
    {
        const int n  = tid >> 2;
        const int dq = (tid & 3) * 16;
        const float* wp = w + n * DEPTH + dq;
        float psum = 0.f;
        #pragma unroll
        for (int i = 0; i < 4; i++) {
            float4 v = reinterpret_cast<const float4*>(wp)[i];
            psum += v.x * v.x + v.y * v.y + v.z * v.z + v.w * v.w;
        }
        psum += __shfl_xor_sync(0xffffffffu, psum, 1);
        psum += __shfl_xor_sync(0xffffffffu, psum, 2);
        if ((tid & 3) == 0) w2_s[n] = psum;
    }

    // ---- Prologue: pack w into uint4 B-fragments (512 entries, 2 per thread).
    #pragma unroll
    for (int e = tid; e < 512; e += 256) {
        const int l   = e & 31;
        const int idx = e >> 5;          // nt*2 + kh
        const int kh  = idx & 1;
        const int nt  = idx >> 1;
        const int n   = nt * 8 + (l >> 2);
        const int k0  = (2 * kh) * 16 + (l & 3) * 2;
        const float* wn = w + n * DEPTH;
        float2 a0 = *reinterpret_cast<const float2*>(wn + k0);
        float2 a1 = *reinterpret_cast<const float2*>(wn + k0 + 8);
        float2 b0 = *reinterpret_cast<const float2*>(wn + k0 + 16);
        float2 b1 = *reinterpret_cast<const float2*>(wn + k0 + 24);
        uint4 f;
        f.x = pack_bf16x2(a0.x, a0.y);
        f.y = pack_bf16x2(a1.x, a1.y);
        f.z = pack_bf16x2(b0.x, b0.y);
        f.w = pack_bf16x2(b1.x, b1.y);
        fragB4[idx][l] = f;
    }
    __syncthreads();   // fragB + mbar init visible

    const int g  = lane >> 2;
    const int t4 = lane & 3;
    char* buf = smem + OFF_BUF + warp * 4096;   // tile bufs, then 2x2KB store slots

    // ---- Consume both tiles (16 rows each) with deep load pipeline.
    float sq[2][8];
    #pragma unroll
    for (int t = 0; t < 2; t++) {
        mbar_wait(t ? mbar1 : mbar0, 0);
        const float4* xt = reinterpret_cast<const float4*>(
            stage + t * 8192 + warp * (16 * DEPTH));
        char* buft = buf + t * 2048;
        #pragma unroll
        for (int i = 0; i < 8; i++) {
            const int ci = i * 32 + lane;
            float4 v = xt[ci];
            sq[t][i] = v.x * v.x + v.y * v.y + v.z * v.z + v.w * v.w;
            const int r     = ci >> 4;
            const int col4  = ci & 15;
            const int ch    = col4 >> 1;
            const int half8 = col4 & 1;
            const int rx    = (r & 7) ^ ((r & 8) >> 1);
            uint2 h;
            h.x = pack_bf16x2(v.x, v.y);
            h.y = pack_bf16x2(v.z, v.w);
            *reinterpret_cast<uint2*>(buft + r * 128 + ((ch ^ rx) * 16) + half8 * 8) = h;
        }
    }
    __syncwarp();

    // ---- A fragments via ldmatrix.x4 (both tiles).
    uint32_t ab[2][4][4];
    {
        const int row   = (lane & 7) + ((lane >> 3) & 1) * 8;
        const int chsel = (lane >> 4);
        const int rx    = (row & 7) ^ ((row & 8) >> 1);
        #pragma unroll
        for (int t = 0; t < 2; t++) {
            const uint32_t base = smem_u32(buf + t * 2048 + row * 128);
            #pragma unroll
            for (int kb = 0; kb < 4; kb++) {
                const int phys = (2 * kb + chsel) ^ rx;
                ldsm_x4(ab[t][kb], base + phys * 16);
            }
        }
    }

    // ---- Deferred x2 reductions.
    #pragma unroll
    for (int t = 0; t < 2; t++) {
        #pragma unroll
        for (int i = 0; i < 8; i++) {
            sq[t][i] += __shfl_xor_sync(0xffffffffu, sq[t][i], 1);
            sq[t][i] += __shfl_xor_sync(0xffffffffu, sq[t][i], 2);
            sq[t][i] += __shfl_xor_sync(0xffffffffu, sq[t][i], 4);
            sq[t][i] += __shfl_xor_sync(0xffffffffu, sq[t][i], 8);
        }
    }
    if (lane == 0) {
        #pragma unroll
        for (int t = 0; t < 2; t++)
            #pragma unroll
            for (int i = 0; i < 8; i++) x2s[warp * 32 + 16 * t + 2 * i] = sq[t][i];
    } else if (lane == 16) {
        #pragma unroll
        for (int t = 0; t < 2; t++)
            #pragma unroll
            for (int i = 0; i < 8; i++) x2s[warp * 32 + 16 * t + 2 * i + 1] = sq[t][i];
    }

    // ---- GEMM: B fragments read ONCE per pair of m-tiles.
    float acc[2][8][4];
    #pragma unroll
    for (int nt = 0; nt < 8; nt++) {
        #pragma unroll
        for (int t = 0; t < 2; t++)
            acc[t][nt][0] = acc[t][nt][1] = acc[t][nt][2] = acc[t][nt][3] = 0.f;
        uint4 bA = fragB4[nt * 2][lane];
        uint4 bB = fragB4[nt * 2 + 1][lane];
        #pragma unroll
        for (int t = 0; t < 2; t++) {
            mma_bf16(acc[t][nt], ab[t][0][0], ab[t][0][1], ab[t][0][2], ab[t][0][3], bA.x, bA.y);
            mma_bf16(acc[t][nt], ab[t][1][0], ab[t][1][1], ab[t][1][2], ab[t][1][3], bA.z, bA.w);
            mma_bf16(acc[t][nt], ab[t][2][0], ab[t][2][1], ab[t][2][2], ab[t][2][3], bB.x, bB.y);
            mma_bf16(acc[t][nt], ab[t][3][0], ab[t][3][1], ab[t][3][2], ab[t][3][3], bB.z, bB.w);
        }
    }
    __syncwarp();   // tile-buf reads done; buf reused as 2 x 2KB store slots

    // ---- Epilogue: out = x2 + w2 - 2*acc. Stage 8 rows (2KB, LINEAR with
    //      bank-rotated nt order) -> cp.async.bulk S2G. 4 stores, 2 slots.
    int k = 0;
    #pragma unroll
    for (int t = 0; t < 2; t++) {
        const float p_lo = x2s[warp * 32 + 16 * t + g];
        const float p_hi = x2s[warp * 32 + 16 * t + g + 8];
        #pragma unroll
        for (int pass = 0; pass < 2; pass++) {
            if (k >= 2) {               // slot (k&1) reused: its store must be done
                if (lane == 0) bulk_wait_group<1>();
                __syncwarp();
            }
            float2* slot = reinterpret_cast<float2*>(buf + (k & 1) * 2048);
            const float p = pass ? p_hi : p_lo;
            #pragma unroll
            for (int j = 0; j < 8; j++) {
                const int nt   = (j + g) & 7;          // bank rotation
                const int ucol = nt * 8 + t4 * 2;
                float2 w2v = *reinterpret_cast<const float2*>(&w2_s[ucol]);
                float2 o;
                o.x = p + w2v.x - 2.f * acc[t][nt][2 * pass];
                o.y = p + w2v.y - 2.f * acc[t][nt][2 * pass + 1];
                slot[g * 32 + nt * 4 + t4] = o;        // linear: row g, col ucol
            }
            __syncwarp();
            if (lane == 0) {
                fence_proxy_async_();
                const long grow = ctarow + t * CHUNK_ROWS + warp * 16 + pass * 8;
                bulk_copy_s2g(out + grow * UNITS, smem_u32(slot), 2048);
                bulk_commit();
            }
            k++;
        }
    }
    if (lane == 0) bulk_wait_group<0>();   // smem must outlive pending stores
}

extern "C" void kernel_launch(void* const* d_in, const int* in_sizes, int n_in,
                              void* d_out, int out_size) {
    const float* x = (const float*)d_in[0];
    const float* w = (const float*)d_in[1];
    float* out = (float*)d_out;
    cudaFuncSetAttribute(sqdist_kernel,
                         cudaFuncAttributeMaxDynamicSharedMemorySize, SMEM_TOTAL);
    const int M = in_sizes[0] / DEPTH;   // 524288
    const int grid = M / 256;            // 2048
    sqdist_kernel<<<grid, 256, SMEM_TOTAL>>>(x, w, out);
}

// round 12
// speedup vs baseline: 1.2901x; 1.2901x over previous
#include <cuda_runtime.h>
#include <cuda_bf16.h>
#include <cstdint>

// out[m,u] = ||x_m||^2 - 2*(x_m . w_u) + ||w_u||^2
// M = 524288, D = 64, U = 64. bf16 mma.sync m16n8k16 cross term.
// 3 CTAs/SM (lean 1-tile warps), 128-row CTA, TMA bulk input. The input
// stage buffer is recycled in place as the output stage (per-warp region
// identity), then ONE 32KB bulk S2G per CTA writes the tile out.

#define DEPTH 64
#define UNITS 64
#define CHUNK_ROWS 128
#define CHUNK_BYTES (CHUNK_ROWS * DEPTH * 4)   // 32768

// dynamic smem layout
#define OFF_STAGE  0                    // 32768 (input f32 / output f32, recycled)
#define OFF_BUF    32768                // 8 warps x 2048 bf16 tile bufs
#define OFF_FRAGB  49152                // 16*32*16 = 8192
#define OFF_W2     57344                // 256
#define OFF_X2     57600                // 8*16*4 = 512
#define OFF_MBAR   58112                // 8
#define SMEM_TOTAL 58120

__device__ __forceinline__ uint32_t pack_bf16x2(float lo, float hi) {
    uint32_t r;
    asm("cvt.rn.bf16x2.f32 %0, %1, %2;" : "=r"(r) : "f"(hi), "f"(lo));
    return r;
}

__device__ __forceinline__ void mma_bf16(float c[4],
                                         uint32_t a0, uint32_t a1, uint32_t a2, uint32_t a3,
                                         uint32_t b0, uint32_t b1) {
    asm volatile(
        "mma.sync.aligned.m16n8k16.row.col.f32.bf16.bf16.f32 "
        "{%0,%1,%2,%3}, {%4,%5,%6,%7}, {%8,%9}, {%0,%1,%2,%3};"
        : "+f"(c[0]), "+f"(c[1]), "+f"(c[2]), "+f"(c[3])
        : "r"(a0), "r"(a1), "r"(a2), "r"(a3), "r"(b0), "r"(b1));
}

__device__ __forceinline__ void ldsm_x4(uint32_t r[4], uint32_t smem_addr) {
    asm volatile("ldmatrix.sync.aligned.m8n8.x4.shared.b16 {%0,%1,%2,%3}, [%4];"
                 : "=r"(r[0]), "=r"(r[1]), "=r"(r[2]), "=r"(r[3])
                 : "r"(smem_addr));
}

__device__ __forceinline__ uint32_t smem_u32(const void* p) {
    return (uint32_t)__cvta_generic_to_shared(p);
}

__device__ __forceinline__ void mbar_init(uint32_t mbar, uint32_t count) {
    asm volatile("mbarrier.init.shared.b64 [%0], %1;" :: "r"(mbar), "r"(count) : "memory");
}
__device__ __forceinline__ void mbar_expect_tx(uint32_t mbar, uint32_t bytes) {
    asm volatile("mbarrier.arrive.expect_tx.shared.b64 _, [%0], %1;"
                 :: "r"(mbar), "r"(bytes) : "memory");
}
__device__ __forceinline__ void bulk_copy_g2s(uint32_t dst, const void* src,
                                              uint32_t bytes, uint32_t mbar) {
    asm volatile(
        "cp.async.bulk.shared::cluster.global.mbarrier::complete_tx::bytes "
        "[%0], [%1], %2, [%3];"
        :: "r"(dst), "l"(src), "r"(bytes), "r"(mbar) : "memory");
}
__device__ __forceinline__ void bulk_copy_s2g(void* dst, uint32_t src_smem,
                                              uint32_t bytes) {
    asm volatile(
        "cp.async.bulk.global.shared::cta.bulk_group [%0], [%1], %2;"
        :: "l"(dst), "r"(src_smem), "r"(bytes) : "memory");
}
__device__ __forceinline__ void bulk_commit() {
    asm volatile("cp.async.bulk.commit_group;" ::: "memory");
}
template <int N>
__device__ __forceinline__ void bulk_wait_group() {
    asm volatile("cp.async.bulk.wait_group %0;" :: "n"(N) : "memory");
}
__device__ __forceinline__ void fence_proxy_async_() {
    asm volatile("fence.proxy.async;" ::: "memory");
}
__device__ __forceinline__ void mbar_wait(uint32_t mbar, uint32_t parity) {
    uint32_t done;
    asm volatile(
        "{\n\t.reg .pred p;\n\t"
        "mbarrier.try_wait.parity.acquire.cta.shared::cta.b64 p, [%1], %2;\n\t"
        "selp.b32 %0, 1, 0, p;\n\t}"
        : "=r"(done) : "r"(mbar), "r"(parity) : "memory");
    if (!done) {
        asm volatile(
            "{\n\t.reg .pred P1;\n\t"
            "WAIT_LOOP_%=:\n\t"
            "mbarrier.try_wait.parity.acquire.cta.shared::cta.b64 P1, [%0], %1, 0x989680;\n\t"
            "@P1 bra.uni WAIT_DONE_%=;\n\t"
            "bra.uni WAIT_LOOP_%=;\n\t"
            "WAIT_DONE_%=:\n\t}"
            :: "r"(mbar), "r"(parity) : "memory");
    }
}

__global__ __launch_bounds__(256, 3) void sqdist_kernel(
    const float* __restrict__ x, const float* __restrict__ w,
    float* __restrict__ out)
{
    extern __shared__ __align__(16) char smem[];
    float* stage = reinterpret_cast<float*>(smem + OFF_STAGE);
    uint4 (*fragB4)[32] = reinterpret_cast<uint4(*)[32]>(smem + OFF_FRAGB);
    float* w2_s  = reinterpret_cast<float*>(smem + OFF_W2);
    float* x2s   = reinterpret_cast<float*>(smem + OFF_X2);   // [8][16]
    const uint32_t mbar0 = smem_u32(smem + OFF_MBAR);

    const int tid  = threadIdx.x;
    const int warp = tid >> 5;
    const int lane = tid & 31;

    const long ctarow = (long)blockIdx.x * CHUNK_ROWS;
    const float* xbase = x + ctarow * DEPTH;

    // ---- TMA input issued FIRST (overlaps prologue).
    if (tid == 0) {
        mbar_init(mbar0, 1);
        mbar_expect_tx(mbar0, CHUNK_BYTES);
        bulk_copy_g2s(smem_u32(stage), xbase, CHUNK_BYTES, mbar0);
    }

    // ---- Prologue: w2 (fp32)
    {
        const int n  = tid >> 2;
        const int dq = (tid & 3) * 16;
        const float* wp = w + n * DEPTH + dq;
        float psum = 0.f;
        #pragma unroll
        for (int i = 0; i < 4; i++) {
            float4 v = reinterpret_cast<const float4*>(wp)[i];
            psum += v.x * v.x + v.y * v.y + v.z * v.z + v.w * v.w;
        }
        psum += __shfl_xor_sync(0xffffffffu, psum, 1);
        psum += __shfl_xor_sync(0xffffffffu, psum, 2);
        if ((tid & 3) == 0) w2_s[n] = psum;
    }

    // ---- Prologue: pack w into uint4 B-fragments (512 entries, 2 per thread).
    #pragma unroll
    for (int e = tid; e < 512; e += 256) {
        const int l   = e & 31;
        const int idx = e >> 5;          // nt*2 + kh
        const int kh  = idx & 1;
        const int nt  = idx >> 1;
        const int n   = nt * 8 + (l >> 2);
        const int k0  = (2 * kh) * 16 + (l & 3) * 2;
        const float* wn = w + n * DEPTH;
        float2 a0 = *reinterpret_cast<const float2*>(wn + k0);
        float2 a1 = *reinterpret_cast<const float2*>(wn + k0 + 8);
        float2 b0 = *reinterpret_cast<const float2*>(wn + k0 + 16);
        float2 b1 = *reinterpret_cast<const float2*>(wn + k0 + 24);
        uint4 f;
        f.x = pack_bf16x2(a0.x, a0.y);
        f.y = pack_bf16x2(a1.x, a1.y);
        f.z = pack_bf16x2(b0.x, b0.y);
        f.w = pack_bf16x2(b1.x, b1.y);
        fragB4[idx][l] = f;
    }
    __syncthreads();   // fragB + mbar init visible

    const int g  = lane >> 2;
    const int t4 = lane & 3;
    char* buf = smem + OFF_BUF + warp * 2048;

    // ---- Wait for input, consume warp's 16-row region (LDS.128 from smem).
    mbar_wait(mbar0, 0);
    const float4* xt = reinterpret_cast<const float4*>(stage + warp * (16 * DEPTH));
    float sq[8];
    #pragma unroll
    for (int i = 0; i < 8; i++) {
        const int ci = i * 32 + lane;
        float4 v = xt[ci];
        sq[i] = v.x * v.x + v.y * v.y + v.z * v.z + v.w * v.w;
        const int r     = ci >> 4;
        const int col4  = ci & 15;
        const int ch    = col4 >> 1;
        const int half8 = col4 & 1;
        const int rx    = (r & 7) ^ ((r & 8) >> 1);
        uint2 h;
        h.x = pack_bf16x2(v.x, v.y);
        h.y = pack_bf16x2(v.z, v.w);
        *reinterpret_cast<uint2*>(buf + r * 128 + ((ch ^ rx) * 16) + half8 * 8) = h;
    }
    __syncwarp();

    // ---- A fragments via ldmatrix.x4.
    uint32_t ab[4][4];
    {
        const int row   = (lane & 7) + ((lane >> 3) & 1) * 8;
        const int chsel = (lane >> 4);
        const int rx    = (row & 7) ^ ((row & 8) >> 1);
        const uint32_t base = smem_u32(buf + row * 128);
        #pragma unroll
        for (int kb = 0; kb < 4; kb++) {
            const int phys = (2 * kb + chsel) ^ rx;
            ldsm_x4(ab[kb], base + phys * 16);
        }
    }

    // ---- x2 reductions.
    #pragma unroll
    for (int i = 0; i < 8; i++) {
        sq[i] += __shfl_xor_sync(0xffffffffu, sq[i], 1);
        sq[i] += __shfl_xor_sync(0xffffffffu, sq[i], 2);
        sq[i] += __shfl_xor_sync(0xffffffffu, sq[i], 4);
        sq[i] += __shfl_xor_sync(0xffffffffu, sq[i], 8);
    }
    if (lane == 0) {
        #pragma unroll
        for (int i = 0; i < 8; i++) x2s[warp * 16 + 2 * i] = sq[i];
    } else if (lane == 16) {
        #pragma unroll
        for (int i = 0; i < 8; i++) x2s[warp * 16 + 2 * i + 1] = sq[i];
    }
    __syncwarp();

    // ---- GEMM: 8 n-tiles x 4 k-blocks, B fragments from smem.
    float acc[8][4];
    #pragma unroll
    for (int nt = 0; nt < 8; nt++) {
        acc[nt][0] = acc[nt][1] = acc[nt][2] = acc[nt][3] = 0.f;
        uint4 bA = fragB4[nt * 2][lane];
        uint4 bB = fragB4[nt * 2 + 1][lane];
        mma_bf16(acc[nt], ab[0][0], ab[0][1], ab[0][2], ab[0][3], bA.x, bA.y);
        mma_bf16(acc[nt], ab[1][0], ab[1][1], ab[1][2], ab[1][3], bA.z, bA.w);
        mma_bf16(acc[nt], ab[2][0], ab[2][1], ab[2][2], ab[2][3], bB.x, bB.y);
        mma_bf16(acc[nt], ab[3][0], ab[3][1], ab[3][2], ab[3][3], bB.z, bB.w);
    }

    // ---- Epilogue IN PLACE: overwrite this warp's (fully consumed) input
    //      region of the stage with output rows. Bank-rotated nt order.
    float2* oreg = reinterpret_cast<float2*>(stage + warp * (16 * DEPTH));
    const float p_lo = x2s[warp * 16 + g];
    const float p_hi = x2s[warp * 16 + g + 8];
    #pragma unroll
    for (int pass = 0; pass < 2; pass++) {
        const float p = pass ? p_hi : p_lo;
        const int r = pass * 8 + g;            // row within warp region
        #pragma unroll
        for (int j = 0; j < 8; j++) {
            const int nt   = (j + g) & 7;      // bank rotation
            const int ucol = nt * 8 + t4 * 2;
            float2 w2v = *reinterpret_cast<const float2*>(&w2_s[ucol]);
            float2 o;
            o.x = p + w2v.x - 2.f * acc[nt][2 * pass];
            o.y = p + w2v.y - 2.f * acc[nt][2 * pass + 1];
            oreg[r * 32 + nt * 4 + t4] = o;    // linear layout == global layout
        }
    }
    __syncthreads();   // whole 32KB output tile staged

    // ---- ONE bulk S2G for the CTA's 32KB output tile.
    if (tid == 0) {
        fence_proxy_async_();
        bulk_copy_s2g(out + ctarow * UNITS, smem_u32(stage), CHUNK_BYTES);
        bulk_commit();
        bulk_wait_group<0>();
    }
    __syncthreads();   // smem must outlive the bulk store
}

extern "C" void kernel_launch(void* const* d_in, const int* in_sizes, int n_in,
                              void* d_out, int out_size) {
    const float* x = (const float*)d_in[0];
    const float* w = (const float*)d_in[1];
    float* out = (float*)d_out;
    cudaFuncSetAttribute(sqdist_kernel,
                         cudaFuncAttributeMaxDynamicSharedMemorySize, SMEM_TOTAL);
    const int M = in_sizes[0] / DEPTH;   // 524288
    const int grid = M / CHUNK_ROWS;     // 4096
    sqdist_kernel<<<grid, 256, SMEM_TOTAL>>>(x, w, out);
}

// round 14
// speedup vs baseline: 1.5452x; 1.1977x over previous
#include <cuda_runtime.h>
#include <cuda_bf16.h>
#include <cstdint>

// out[m,u] = ||x_m||^2 - 2*(x_m . w_u) + ||w_u||^2
// M = 524288, D = 64, U = 64. bf16 mma.sync m16n8k16 cross term.
// R14 = R12 front half (TMA bulk input, lean 1-tile warps, 3 CTAs/SM)
//     + R9 staged-swizzle STG epilogue (the proven store path).

#define DEPTH 64
#define UNITS 64
#define CHUNK_ROWS 128
#define CHUNK_BYTES (CHUNK_ROWS * DEPTH * 4)   // 32768

// dynamic smem layout
#define OFF_STAGE  0                    // 32768 (TMA input stage, f32)
#define OFF_BUF    32768                // 8 warps x 2048 (bf16 tile / epi stage)
#define OFF_FRAGB  49152                // 16*32*16 = 8192
#define OFF_W2     57344                // 256
#define OFF_X2     57600                // 8*16*4 = 512
#define OFF_MBAR   58112                // 8
#define SMEM_TOTAL 58120

__device__ __forceinline__ uint32_t pack_bf16x2(float lo, float hi) {
    uint32_t r;
    asm("cvt.rn.bf16x2.f32 %0, %1, %2;" : "=r"(r) : "f"(hi), "f"(lo));
    return r;
}

__device__ __forceinline__ void mma_bf16(float c[4],
                                         uint32_t a0, uint32_t a1, uint32_t a2, uint32_t a3,
                                         uint32_t b0, uint32_t b1) {
    asm volatile(
        "mma.sync.aligned.m16n8k16.row.col.f32.bf16.bf16.f32 "
        "{%0,%1,%2,%3}, {%4,%5,%6,%7}, {%8,%9}, {%0,%1,%2,%3};"
        : "+f"(c[0]), "+f"(c[1]), "+f"(c[2]), "+f"(c[3])
        : "r"(a0), "r"(a1), "r"(a2), "r"(a3), "r"(b0), "r"(b1));
}

__device__ __forceinline__ void ldsm_x4(uint32_t r[4], uint32_t smem_addr) {
    asm volatile("ldmatrix.sync.aligned.m8n8.x4.shared.b16 {%0,%1,%2,%3}, [%4];"
                 : "=r"(r[0]), "=r"(r[1]), "=r"(r[2]), "=r"(r[3])
                 : "r"(smem_addr));
}

__device__ __forceinline__ uint32_t smem_u32(const void* p) {
    return (uint32_t)__cvta_generic_to_shared(p);
}

__device__ __forceinline__ void mbar_init(uint32_t mbar, uint32_t count) {
    asm volatile("mbarrier.init.shared.b64 [%0], %1;" :: "r"(mbar), "r"(count) : "memory");
}
__device__ __forceinline__ void mbar_expect_tx(uint32_t mbar, uint32_t bytes) {
    asm volatile("mbarrier.arrive.expect_tx.shared.b64 _, [%0], %1;"
                 :: "r"(mbar), "r"(bytes) : "memory");
}
__device__ __forceinline__ void bulk_copy_g2s(uint32_t dst, const void* src,
                                              uint32_t bytes, uint32_t mbar) {
    asm volatile(
        "cp.async.bulk.shared::cluster.global.mbarrier::complete_tx::bytes "
        "[%0], [%1], %2, [%3];"
        :: "r"(dst), "l"(src), "r"(bytes), "r"(mbar) : "memory");
}
__device__ __forceinline__ void mbar_wait(uint32_t mbar, uint32_t parity) {
    uint32_t done;
    asm volatile(
        "{\n\t.reg .pred p;\n\t"
        "mbarrier.try_wait.parity.acquire.cta.shared::cta.b64 p, [%1], %2;\n\t"
        "selp.b32 %0, 1, 0, p;\n\t}"
        : "=r"(done) : "r"(mbar), "r"(parity) : "memory");
    if (!done) {
        asm volatile(
            "{\n\t.reg .pred P1;\n\t"
            "WAIT_LOOP_%=:\n\t"
            "mbarrier.try_wait.parity.acquire.cta.shared::cta.b64 P1, [%0], %1, 0x989680;\n\t"
            "@P1 bra.uni WAIT_DONE_%=;\n\t"
            "bra.uni WAIT_LOOP_%=;\n\t"
            "WAIT_DONE_%=:\n\t}"
            :: "r"(mbar), "r"(parity) : "memory");
    }
}

__global__ __launch_bounds__(256, 3) void sqdist_kernel(
    const float* __restrict__ x, const float* __restrict__ w,
    float* __restrict__ out)
{
    extern __shared__ __align__(16) char smem[];
    float* stage = reinterpret_cast<float*>(smem + OFF_STAGE);
    uint4 (*fragB4)[32] = reinterpret_cast<uint4(*)[32]>(smem + OFF_FRAGB);
    float* w2_s  = reinterpret_cast<float*>(smem + OFF_W2);
    float* x2s   = reinterpret_cast<float*>(smem + OFF_X2);   // [8][16]
    const uint32_t mbar0 = smem_u32(smem + OFF_MBAR);

    const int tid  = threadIdx.x;
    const int warp = tid >> 5;
    const int lane = tid & 31;

    const long ctarow = (long)blockIdx.x * CHUNK_ROWS;
    const float* xbase = x + ctarow * DEPTH;

    // ---- TMA input issued FIRST (overlaps prologue).
    if (tid == 0) {
        mbar_init(mbar0, 1);
        mbar_expect_tx(mbar0, CHUNK_BYTES);
        bulk_copy_g2s(smem_u32(stage), xbase, CHUNK_BYTES, mbar0);
    }

    // ---- Prologue: w2 (fp32)
    {
        const int n  = tid >> 2;
        const int dq = (tid & 3) * 16;
        const float* wp = w + n * DEPTH + dq;
        float psum = 0.f;
        #pragma unroll
        for (int i = 0; i < 4; i++) {
            float4 v = reinterpret_cast<const float4*>(wp)[i];
            psum += v.x * v.x + v.y * v.y + v.z * v.z + v.w * v.w;
        }
        psum += __shfl_xor_sync(0xffffffffu, psum, 1);
        psum += __shfl_xor_sync(0xffffffffu, psum, 2);
        if ((tid & 3) == 0) w2_s[n] = psum;
    }

    // ---- Prologue: pack w into uint4 B-fragments (512 entries, 2 per thread).
    #pragma unroll
    for (int e = tid; e < 512; e += 256) {
        const int l   = e & 31;
        const int idx = e >> 5;          // nt*2 + kh
        const int kh  = idx & 1;
        const int nt  = idx >> 1;
        const int n   = nt * 8 + (l >> 2);
        const int k0  = (2 * kh) * 16 + (l & 3) * 2;
        const float* wn = w + n * DEPTH;
        float2 a0 = *reinterpret_cast<const float2*>(wn + k0);
        float2 a1 = *reinterpret_cast<const float2*>(wn + k0 + 8);
        float2 b0 = *reinterpret_cast<const float2*>(wn + k0 + 16);
        float2 b1 = *reinterpret_cast<const float2*>(wn + k0 + 24);
        uint4 f;
        f.x = pack_bf16x2(a0.x, a0.y);
        f.y = pack_bf16x2(a1.x, a1.y);
        f.z = pack_bf16x2(b0.x, b0.y);
        f.w = pack_bf16x2(b1.x, b1.y);
        fragB4[idx][l] = f;
    }
    __syncthreads();   // fragB + mbar init visible

    const int g  = lane >> 2;
    const int t4 = lane & 3;
    char* buf = smem + OFF_BUF + warp * 2048;

    // ---- Wait for input, consume warp's 16-row region (LDS.128 from smem).
    mbar_wait(mbar0, 0);
    const float4* xt = reinterpret_cast<const float4*>(stage + warp * (16 * DEPTH));
    float sq[8];
    #pragma unroll
    for (int i = 0; i < 8; i++) {
        const int ci = i * 32 + lane;
        float4 v = xt[ci];
        sq[i] = v.x * v.x + v.y * v.y + v.z * v.z + v.w * v.w;
        const int r     = ci >> 4;
        const int col4  = ci & 15;
        const int ch    = col4 >> 1;
        const int half8 = col4 & 1;
        const int rx    = (r & 7) ^ ((r & 8) >> 1);
        uint2 h;
        h.x = pack_bf16x2(v.x, v.y);
        h.y = pack_bf16x2(v.z, v.w);
        *reinterpret_cast<uint2*>(buf + r * 128 + ((ch ^ rx) * 16) + half8 * 8) = h;
    }
    __syncwarp();

    // ---- A fragments via ldmatrix.x4.
    uint32_t ab[4][4];
    {
        const int row   = (lane & 7) + ((lane >> 3) & 1) * 8;
        const int chsel = (lane >> 4);
        const int rx    = (row & 7) ^ ((row & 8) >> 1);
        const uint32_t base = smem_u32(buf + row * 128);
        #pragma unroll
        for (int kb = 0; kb < 4; kb++) {
            const int phys = (2 * kb + chsel) ^ rx;
            ldsm_x4(ab[kb], base + phys * 16);
        }
    }

    // ---- x2 reductions.
    #pragma unroll
    for (int i = 0; i < 8; i++) {
        sq[i] += __shfl_xor_sync(0xffffffffu, sq[i], 1);
        sq[i] += __shfl_xor_sync(0xffffffffu, sq[i], 2);
        sq[i] += __shfl_xor_sync(0xffffffffu, sq[i], 4);
        sq[i] += __shfl_xor_sync(0xffffffffu, sq[i], 8);
    }
    if (lane == 0) {
        #pragma unroll
        for (int i = 0; i < 8; i++) x2s[warp * 16 + 2 * i] = sq[i];
    } else if (lane == 16) {
        #pragma unroll
        for (int i = 0; i < 8; i++) x2s[warp * 16 + 2 * i + 1] = sq[i];
    }
    __syncwarp();

    // ---- GEMM: 8 n-tiles x 4 k-blocks, B fragments from smem.
    float acc[8][4];
    #pragma unroll
    for (int nt = 0; nt < 8; nt++) {
        acc[nt][0] = acc[nt][1] = acc[nt][2] = acc[nt][3] = 0.f;
        uint4 bA = fragB4[nt * 2][lane];
        uint4 bB = fragB4[nt * 2 + 1][lane];
        mma_bf16(acc[nt], ab[0][0], ab[0][1], ab[0][2], ab[0][3], bA.x, bA.y);
        mma_bf16(acc[nt], ab[1][0], ab[1][1], ab[1][2], ab[1][3], bA.z, bA.w);
        mma_bf16(acc[nt], ab[2][0], ab[2][1], ab[2][2], ab[2][3], bB.x, bB.y);
        mma_bf16(acc[nt], ab[3][0], ab[3][1], ab[3][2], ab[3][3], bB.z, bB.w);
    }
    __syncwarp();   // bf16 tile reads done; buf reused as epilogue stage

    // ---- Epilogue (R9 scheme): out = x2 + w2 - 2*acc, staged swizzled
    //      -> coalesced STG.128, 2 passes of 8 rows.
    float2* stage2 = reinterpret_cast<float2*>(buf);   // 8 rows x 32 float2
    const int jj   = lane & 15;
    const int rhal = lane >> 4;
    const long row0 = ctarow + warp * 16;
    const float p_lo = x2s[warp * 16 + g];
    const float p_hi = x2s[warp * 16 + g + 8];
    #pragma unroll
    for (int pass = 0; pass < 2; pass++) {
        const float p = pass ? p_hi : p_lo;
        #pragma unroll
        for (int nt = 0; nt < 8; nt++) {
            const int ucol = nt * 8 + t4 * 2;
            float2 w2v = *reinterpret_cast<const float2*>(&w2_s[ucol]);
            float2 o;
            o.x = p + w2v.x - 2.f * acc[nt][2 * pass];
            o.y = p + w2v.y - 2.f * acc[nt][2 * pass + 1];
            const int sidx = nt * 4 + t4;
            stage2[g * 32 + (sidx ^ ((g & 3) * 4))] = o;
        }
        __syncwarp();
        #pragma unroll
        for (int s8 = 0; s8 < 4; s8++) {
            const int r = s8 * 2 + rhal;
            const int phys = (2 * jj) ^ ((r & 3) * 4);
            float4 v = *reinterpret_cast<const float4*>(&stage2[r * 32 + phys]);
            const long grow = row0 + pass * 8 + r;
            __stcs(reinterpret_cast<float4*>(out + grow * UNITS + jj * 4), v);
        }
        __syncwarp();
    }
}

extern "C" void kernel_launch(void* const* d_in, const int* in_sizes, int n_in,
                              void* d_out, int out_size) {
    const float* x = (const float*)d_in[0];
    const float* w = (const float*)d_in[1];
    float* out = (float*)d_out;
    cudaFuncSetAttribute(sqdist_kernel,
                         cudaFuncAttributeMaxDynamicSharedMemorySize, SMEM_TOTAL);
    const int M = in_sizes[0] / DEPTH;   // 524288
    const int grid = M / CHUNK_ROWS;     // 4096
    sqdist_kernel<<<grid, 256, SMEM_TOTAL>>>(x, w, out);
}

// round 15
// speedup vs baseline: 1.7281x; 1.1184x over previous
#include <cuda_runtime.h>
#include <cuda_fp16.h>
#include <cstdint>

// out[m,u] = ||x_m||^2 - 2*(x_m . w_u) + ||w_u||^2
// M = 524288, D = 64, U = 64. f16 mma.sync m16n8k16 with F16 ACCUMULATORS
// (halves acc registers -> 3 CTAs/SM with the 2-tile fragB-amortized design).
// TMA bulk input, deep-pipeline consume, deferred x2 shuffles (exact fp32),
// staged-swizzle STG.128 epilogue. Structure otherwise identical to R9.

#define DEPTH 64
#define UNITS 64
#define CHUNK_ROWS 128
#define CHUNK_BYTES (CHUNK_ROWS * DEPTH * 4)   // 32768

// dynamic smem layout
#define OFF_STAGE  0                    // 2 x 32768 (TMA input stages)
#define OFF_BUF    65536                // 8 warps x 4096 (2 x 2KB f16 tiles / epi stage)
#define OFF_FRAGB  98304                // 16*32*16 = 8192
#define OFF_W2     106496               // 256
#define OFF_X2     106752               // 8*32*4 = 1024
#define OFF_MBAR   107776               // 16
#define SMEM_TOTAL 107800

__device__ __forceinline__ uint32_t pack_f16x2(float lo, float hi) {
    uint32_t r;
    asm("cvt.rn.f16x2.f32 %0, %1, %2;" : "=r"(r) : "f"(hi), "f"(lo));
    return r;
}

// m16n8k16, f16 inputs, F16 accumulators (2 x u32 = 4 halves).
__device__ __forceinline__ void mma_f16(uint32_t c[2],
                                        uint32_t a0, uint32_t a1, uint32_t a2, uint32_t a3,
                                        uint32_t b0, uint32_t b1) {
    asm volatile(
        "mma.sync.aligned.m16n8k16.row.col.f16.f16.f16.f16 "
        "{%0,%1}, {%2,%3,%4,%5}, {%6,%7}, {%0,%1};"
        : "+r"(c[0]), "+r"(c[1])
        : "r"(a0), "r"(a1), "r"(a2), "r"(a3), "r"(b0), "r"(b1));
}

__device__ __forceinline__ void ldsm_x4(uint32_t r[4], uint32_t smem_addr) {
    asm volatile("ldmatrix.sync.aligned.m8n8.x4.shared.b16 {%0,%1,%2,%3}, [%4];"
                 : "=r"(r[0]), "=r"(r[1]), "=r"(r[2]), "=r"(r[3])
                 : "r"(smem_addr));
}

__device__ __forceinline__ uint32_t smem_u32(const void* p) {
    return (uint32_t)__cvta_generic_to_shared(p);
}

__device__ __forceinline__ void mbar_init(uint32_t mbar, uint32_t count) {
    asm volatile("mbarrier.init.shared.b64 [%0], %1;" :: "r"(mbar), "r"(count) : "memory");
}
__device__ __forceinline__ void mbar_expect_tx(uint32_t mbar, uint32_t bytes) {
    asm volatile("mbarrier.arrive.expect_tx.shared.b64 _, [%0], %1;"
                 :: "r"(mbar), "r"(bytes) : "memory");
}
__device__ __forceinline__ void bulk_copy_g2s(uint32_t dst, const void* src,
                                              uint32_t bytes, uint32_t mbar) {
    asm volatile(
        "cp.async.bulk.shared::cluster.global.mbarrier::complete_tx::bytes "
        "[%0], [%1], %2, [%3];"
        :: "r"(dst), "l"(src), "r"(bytes), "r"(mbar) : "memory");
}
__device__ __forceinline__ void mbar_wait(uint32_t mbar, uint32_t parity) {
    uint32_t done;
    asm volatile(
        "{\n\t.reg .pred p;\n\t"
        "mbarrier.try_wait.parity.acquire.cta.shared::cta.b64 p, [%1], %2;\n\t"
        "selp.b32 %0, 1, 0, p;\n\t}"
        : "=r"(done) : "r"(mbar), "r"(parity) : "memory");
    if (!done) {
        asm volatile(
            "{\n\t.reg .pred P1;\n\t"
            "WAIT_LOOP_%=:\n\t"
            "mbarrier.try_wait.parity.acquire.cta.shared::cta.b64 P1, [%0], %1, 0x989680;\n\t"
            "@P1 bra.uni WAIT_DONE_%=;\n\t"
            "bra.uni WAIT_LOOP_%=;\n\t"
            "WAIT_DONE_%=:\n\t}"
            :: "r"(mbar), "r"(parity) : "memory");
    }
}

__global__ __launch_bounds__(256, 3) void sqdist_kernel(
    const float* __restrict__ x, const float* __restrict__ w,
    float* __restrict__ out)
{
    extern __shared__ __align__(16) char smem[];
    float* stage = reinterpret_cast<float*>(smem + OFF_STAGE);
    uint4 (*fragB4)[32] = reinterpret_cast<uint4(*)[32]>(smem + OFF_FRAGB);
    float* w2_s  = reinterpret_cast<float*>(smem + OFF_W2);
    float* x2s   = reinterpret_cast<float*>(smem + OFF_X2);   // [8][32]
    const uint32_t mbar0 = smem_u32(smem + OFF_MBAR);
    const uint32_t mbar1 = mbar0 + 8;

    const int tid  = threadIdx.x;
    const int warp = tid >> 5;
    const int lane = tid & 31;

    const long ctarow = (long)blockIdx.x * 256;
    const float* xbase = x + ctarow * DEPTH;

    // ---- Issue both chunk loads FIRST (overlap with prologue).
    if (tid == 0) {
        mbar_init(mbar0, 1);
        mbar_init(mbar1, 1);
        mbar_expect_tx(mbar0, CHUNK_BYTES);
        bulk_copy_g2s(smem_u32(stage), xbase, CHUNK_BYTES, mbar0);
        mbar_expect_tx(mbar1, CHUNK_BYTES);
        bulk_copy_g2s(smem_u32(stage + 8192), xbase + CHUNK_ROWS * DEPTH,
                      CHUNK_BYTES, mbar1);
    }

    // ---- Prologue: w2 (fp32)
    {
        const int n  = tid >> 2;
        const int dq = (tid & 3) * 16;
        const float* wp = w + n * DEPTH + dq;
        float psum = 0.f;
        #pragma unroll
        for (int i = 0; i < 4; i++) {
            float4 v = reinterpret_cast<const float4*>(wp)[i];
            psum += v.x * v.x + v.y * v.y + v.z * v.z + v.w * v.w;
        }
        psum += __shfl_xor_sync(0xffffffffu, psum, 1);
        psum += __shfl_xor_sync(0xffffffffu, psum, 2);
        if ((tid & 3) == 0) w2_s[n] = psum;
    }

    // ---- Prologue: pack w into uint4 B-fragments, f16 (512 entries, 2/thread).
    #pragma unroll
    for (int e = tid; e < 512; e += 256) {
        const int l   = e & 31;
        const int idx = e >> 5;          // nt*2 + kh
        const int kh  = idx & 1;
        const int nt  = idx >> 1;
        const int n   = nt * 8 + (l >> 2);
        const int k0  = (2 * kh) * 16 + (l & 3) * 2;
        const float* wn = w + n * DEPTH;
        float2 a0 = *reinterpret_cast<const float2*>(wn + k0);
        float2 a1 = *reinterpret_cast<const float2*>(wn + k0 + 8);
        float2 b0 = *reinterpret_cast<const float2*>(wn + k0 + 16);
        float2 b1 = *reinterpret_cast<const float2*>(wn + k0 + 24);
        uint4 f;
        f.x = pack_f16x2(a0.x, a0.y);
        f.y = pack_f16x2(a1.x, a1.y);
        f.z = pack_f16x2(b0.x, b0.y);
        f.w = pack_f16x2(b1.x, b1.y);
        fragB4[idx][l] = f;
    }
    __syncthreads();   // fragB + mbar init visible

    const int g  = lane >> 2;
    const int t4 = lane & 3;
    char* buf = smem + OFF_BUF + warp * 4096;   // 2 x 2KB tile bufs / epi stage

    // ---- Consume both tiles (16 rows each) with deep load pipeline.
    float sq[2][8];
    #pragma unroll
    for (int t = 0; t < 2; t++) {
        mbar_wait(t ? mbar1 : mbar0, 0);
        const float4* xt = reinterpret_cast<const float4*>(
            stage + t * 8192 + warp * (16 * DEPTH));
        char* buft = buf + t * 2048;
        #pragma unroll
        for (int i = 0; i < 8; i++) {
            const int ci = i * 32 + lane;
            float4 v = xt[ci];
            sq[t][i] = v.x * v.x + v.y * v.y + v.z * v.z + v.w * v.w;
            const int r     = ci >> 4;
            const int col4  = ci & 15;
            const int ch    = col4 >> 1;
            const int half8 = col4 & 1;
            const int rx    = (r & 7) ^ ((r & 8) >> 1);
            uint2 h;
            h.x = pack_f16x2(v.x, v.y);
            h.y = pack_f16x2(v.z, v.w);
            *reinterpret_cast<uint2*>(buft + r * 128 + ((ch ^ rx) * 16) + half8 * 8) = h;
        }
    }
    __syncwarp();

    // ---- A fragments via ldmatrix.x4 (both tiles).
    uint32_t ab[2][4][4];
    {
        const int row   = (lane & 7) + ((lane >> 3) & 1) * 8;
        const int chsel = (lane >> 4);
        const int rx    = (row & 7) ^ ((row & 8) >> 1);
        #pragma unroll
        for (int t = 0; t < 2; t++) {
            const uint32_t base = smem_u32(buf + t * 2048 + row * 128);
            #pragma unroll
            for (int kb = 0; kb < 4; kb++) {
                const int phys = (2 * kb + chsel) ^ rx;
                ldsm_x4(ab[t][kb], base + phys * 16);
            }
        }
    }

    // ---- Deferred x2 reductions (exact fp32).
    #pragma unroll
    for (int t = 0; t < 2; t++) {
        #pragma unroll
        for (int i = 0; i < 8; i++) {
            sq[t][i] += __shfl_xor_sync(0xffffffffu, sq[t][i], 1);
            sq[t][i] += __shfl_xor_sync(0xffffffffu, sq[t][i], 2);
            sq[t][i] += __shfl_xor_sync(0xffffffffu, sq[t][i], 4);
            sq[t][i] += __shfl_xor_sync(0xffffffffu, sq[t][i], 8);
        }
    }
    if (lane == 0) {
        #pragma unroll
        for (int t = 0; t < 2; t++)
            #pragma unroll
            for (int i = 0; i < 8; i++) x2s[warp * 32 + 16 * t + 2 * i] = sq[t][i];
    } else if (lane == 16) {
        #pragma unroll
        for (int t = 0; t < 2; t++)
            #pragma unroll
            for (int i = 0; i < 8; i++) x2s[warp * 32 + 16 * t + 2 * i + 1] = sq[t][i];
    }

    // ---- GEMM: f16 accumulators, B fragments read ONCE per pair of m-tiles.
    uint32_t acc[2][8][2];   // [tile][nt][row-half], each u32 = f16x2 (2 cols)
    #pragma unroll
    for (int nt = 0; nt < 8; nt++) {
        #pragma unroll
        for (int t = 0; t < 2; t++) { acc[t][nt][0] = 0u; acc[t][nt][1] = 0u; }
        uint4 bA = fragB4[nt * 2][lane];
        uint4 bB = fragB4[nt * 2 + 1][lane];
        #pragma unroll
        for (int t = 0; t < 2; t++) {
            mma_f16(acc[t][nt], ab[t][0][0], ab[t][0][1], ab[t][0][2], ab[t][0][3], bA.x, bA.y);
            mma_f16(acc[t][nt], ab[t][1][0], ab[t][1][1], ab[t][1][2], ab[t][1][3], bA.z, bA.w);
            mma_f16(acc[t][nt], ab[t][2][0], ab[t][2][1], ab[t][2][2], ab[t][2][3], bB.x, bB.y);
            mma_f16(acc[t][nt], ab[t][3][0], ab[t][3][1], ab[t][3][2], ab[t][3][3], bB.z, bB.w);
        }
    }
    __syncwarp();   // tile-buf reads done; buf reused as 4KB epilogue stage

    // ---- Epilogue per tile: stage 16 rows (swizzled), then 8x STG.128.
    float2* stage2 = reinterpret_cast<float2*>(buf);   // 16 rows x 32 float2
    const int jj   = lane & 15;
    const int rhal = lane >> 4;
    #pragma unroll
    for (int t = 0; t < 2; t++) {
        const float p_lo = x2s[warp * 32 + 16 * t + g];
        const float p_hi = x2s[warp * 32 + 16 * t + g + 8];
        #pragma unroll
        for (int pass = 0; pass < 2; pass++) {
            const float p = pass ? p_hi : p_lo;
            const int rr = pass * 8 + g;
            #pragma unroll
            for (int nt = 0; nt < 8; nt++) {
                const int ucol = nt * 8 + t4 * 2;
                float2 w2v = *reinterpret_cast<const float2*>(&w2_s[ucol]);
                const __half2 h = *reinterpret_cast<const __half2*>(&acc[t][nt][pass]);
                const float2 f = __half22float2(h);
                float2 o;
                o.x = p + w2v.x - 2.f * f.x;
                o.y = p + w2v.y - 2.f * f.y;
                const int sidx = nt * 4 + t4;
                stage2[rr * 32 + (sidx ^ ((g & 3) * 4))] = o;
            }
        }
        __syncwarp();
        const long row0 = ctarow + t * CHUNK_ROWS + warp * 16;
        #pragma unroll
        for (int s8 = 0; s8 < 8; s8++) {
            const int r = s8 * 2 + rhal;
            const int phys = (2 * jj) ^ ((r & 3) * 4);
            float4 v = *reinterpret_cast<const float4*>(&stage2[r * 32 + phys]);
            const long grow = row0 + r;
            __stcs(reinterpret_cast<float4*>(out + grow * UNITS + jj * 4), v);
        }
        __syncwarp();
    }
}

extern "C" void kernel_launch(void* const* d_in, const int* in_sizes, int n_in,
                              void* d_out, int out_size) {
    const float* x = (const float*)d_in[0];
    const float* w = (const float*)d_in[1];
    float* out = (float*)d_out;
    cudaFuncSetAttribute(sqdist_kernel,
                         cudaFuncAttributeMaxDynamicSharedMemorySize, SMEM_TOTAL);
    const int M = in_sizes[0] / DEPTH;   // 524288
    const int grid = M / 256;            // 2048
    sqdist_kernel<<<grid, 256, SMEM_TOTAL>>>(x, w, out);
}

// round 16
// speedup vs baseline: 1.8521x; 1.0718x over previous
#include <cuda_runtime.h>
#include <cuda_fp16.h>
#include <cstdint>

// out[m,u] = ||x_m||^2 - 2*(x_m . w_u) + ||w_u||^2
// M = 524288, D = 64, U = 64. f16 mma.sync m16n8k16, F16 accumulators.
// R16 = R15 with the per-warp tile/epilogue buffers ELIMINATED: f16 tiles are
// converted IN PLACE into the TMA input stage (each warp's own 4KB slice),
// and the epilogue stages into the same slice. smem 107.8KB -> 75KB
// -> 3 CTAs/SM with the 2-tile fragB-amortized design intact.

#define DEPTH 64
#define UNITS 64
#define CHUNK_ROWS 128
#define CHUNK_BYTES (CHUNK_ROWS * DEPTH * 4)   // 32768

// dynamic smem layout
#define OFF_STAGE  0                    // 2 x 32768 (TMA input stages; recycled)
#define OFF_FRAGB  65536                // 16*32*16 = 8192
#define OFF_W2     73728                // 256
#define OFF_X2     73984                // 8*32*4 = 1024
#define OFF_MBAR   75008                // 16
#define SMEM_TOTAL 75024

__device__ __forceinline__ uint32_t pack_f16x2(float lo, float hi) {
    uint32_t r;
    asm("cvt.rn.f16x2.f32 %0, %1, %2;" : "=r"(r) : "f"(hi), "f"(lo));
    return r;
}

// m16n8k16, f16 inputs, F16 accumulators (2 x u32 = 4 halves).
__device__ __forceinline__ void mma_f16(uint32_t c[2],
                                        uint32_t a0, uint32_t a1, uint32_t a2, uint32_t a3,
                                        uint32_t b0, uint32_t b1) {
    asm volatile(
        "mma.sync.aligned.m16n8k16.row.col.f16.f16.f16.f16 "
        "{%0,%1}, {%2,%3,%4,%5}, {%6,%7}, {%0,%1};"
        : "+r"(c[0]), "+r"(c[1])
        : "r"(a0), "r"(a1), "r"(a2), "r"(a3), "r"(b0), "r"(b1));
}

__device__ __forceinline__ void ldsm_x4(uint32_t r[4], uint32_t smem_addr) {
    asm volatile("ldmatrix.sync.aligned.m8n8.x4.shared.b16 {%0,%1,%2,%3}, [%4];"
                 : "=r"(r[0]), "=r"(r[1]), "=r"(r[2]), "=r"(r[3])
                 : "r"(smem_addr));
}

__device__ __forceinline__ uint32_t smem_u32(const void* p) {
    return (uint32_t)__cvta_generic_to_shared(p);
}

__device__ __forceinline__ void mbar_init(uint32_t mbar, uint32_t count) {
    asm volatile("mbarrier.init.shared.b64 [%0], %1;" :: "r"(mbar), "r"(count) : "memory");
}
__device__ __forceinline__ void mbar_expect_tx(uint32_t mbar, uint32_t bytes) {
    asm volatile("mbarrier.arrive.expect_tx.shared.b64 _, [%0], %1;"
                 :: "r"(mbar), "r"(bytes) : "memory");
}
__device__ __forceinline__ void bulk_copy_g2s(uint32_t dst, const void* src,
                                              uint32_t bytes, uint32_t mbar) {
    asm volatile(
        "cp.async.bulk.shared::cluster.global.mbarrier::complete_tx::bytes "
        "[%0], [%1], %2, [%3];"
        :: "r"(dst), "l"(src), "r"(bytes), "r"(mbar) : "memory");
}
__device__ __forceinline__ void mbar_wait(uint32_t mbar, uint32_t parity) {
    uint32_t done;
    asm volatile(
        "{\n\t.reg .pred p;\n\t"
        "mbarrier.try_wait.parity.acquire.cta.shared::cta.b64 p, [%1], %2;\n\t"
        "selp.b32 %0, 1, 0, p;\n\t}"
        : "=r"(done) : "r"(mbar), "r"(parity) : "memory");
    if (!done) {
        asm volatile(
            "{\n\t.reg .pred P1;\n\t"
            "WAIT_LOOP_%=:\n\t"
            "mbarrier.try_wait.parity.acquire.cta.shared::cta.b64 P1, [%0], %1, 0x989680;\n\t"
            "@P1 bra.uni WAIT_DONE_%=;\n\t"
            "bra.uni WAIT_LOOP_%=;\n\t"
            "WAIT_DONE_%=:\n\t}"
            :: "r"(mbar), "r"(parity) : "memory");
    }
}

__global__ __launch_bounds__(256, 3) void sqdist_kernel(
    const float* __restrict__ x, const float* __restrict__ w,
    float* __restrict__ out)
{
    extern __shared__ __align__(16) char smem[];
    float* stage = reinterpret_cast<float*>(smem + OFF_STAGE);
    uint4 (*fragB4)[32] = reinterpret_cast<uint4(*)[32]>(smem + OFF_FRAGB);
    float* w2_s  = reinterpret_cast<float*>(smem + OFF_W2);
    float* x2s   = reinterpret_cast<float*>(smem + OFF_X2);   // [8][32]
    const uint32_t mbar0 = smem_u32(smem + OFF_MBAR);
    const uint32_t mbar1 = mbar0 + 8;

    const int tid  = threadIdx.x;
    const int warp = tid >> 5;
    const int lane = tid & 31;

    const long ctarow = (long)blockIdx.x * 256;
    const float* xbase = x + ctarow * DEPTH;

    // ---- Issue both chunk loads FIRST (overlap with prologue).
    if (tid == 0) {
        mbar_init(mbar0, 1);
        mbar_init(mbar1, 1);
        mbar_expect_tx(mbar0, CHUNK_BYTES);
        bulk_copy_g2s(smem_u32(stage), xbase, CHUNK_BYTES, mbar0);
        mbar_expect_tx(mbar1, CHUNK_BYTES);
        bulk_copy_g2s(smem_u32(stage + 8192), xbase + CHUNK_ROWS * DEPTH,
                      CHUNK_BYTES, mbar1);
    }

    // ---- Prologue: w2 (fp32)
    {
        const int n  = tid >> 2;
        const int dq = (tid & 3) * 16;
        const float* wp = w + n * DEPTH + dq;
        float psum = 0.f;
        #pragma unroll
        for (int i = 0; i < 4; i++) {
            float4 v = reinterpret_cast<const float4*>(wp)[i];
            psum += v.x * v.x + v.y * v.y + v.z * v.z + v.w * v.w;
        }
        psum += __shfl_xor_sync(0xffffffffu, psum, 1);
        psum += __shfl_xor_sync(0xffffffffu, psum, 2);
        if ((tid & 3) == 0) w2_s[n] = psum;
    }

    // ---- Prologue: pack w into uint4 B-fragments, f16 (512 entries, 2/thread).
    #pragma unroll
    for (int e = tid; e < 512; e += 256) {
        const int l   = e & 31;
        const int idx = e >> 5;          // nt*2 + kh
        const int kh  = idx & 1;
        const int nt  = idx >> 1;
        const int n   = nt * 8 + (l >> 2);
        const int k0  = (2 * kh) * 16 + (l & 3) * 2;
        const float* wn = w + n * DEPTH;
        float2 a0 = *reinterpret_cast<const float2*>(wn + k0);
        float2 a1 = *reinterpret_cast<const float2*>(wn + k0 + 8);
        float2 b0 = *reinterpret_cast<const float2*>(wn + k0 + 16);
        float2 b1 = *reinterpret_cast<const float2*>(wn + k0 + 24);
        uint4 f;
        f.x = pack_f16x2(a0.x, a0.y);
        f.y = pack_f16x2(a1.x, a1.y);
        f.z = pack_f16x2(b0.x, b0.y);
        f.w = pack_f16x2(b1.x, b1.y);
        fragB4[idx][l] = f;
    }
    __syncthreads();   // fragB + mbar init visible

    const int g  = lane >> 2;
    const int t4 = lane & 3;

    // Each warp's private 4KB slice of each chunk region (input f32; then f16
    // tile in its first 2KB; then epilogue stage).
    char* slice0 = smem + OFF_STAGE + 0 * 32768 + warp * 4096;
    char* slice1 = smem + OFF_STAGE + 1 * 32768 + warp * 4096;

    // ---- Consume both tiles IN PLACE with deep load pipeline.
    //      Writes at iter i touch bytes [256i,256i+256) of the slice; reads at
    //      iter i touch [512i,512i+512) -> every write lands on already-read
    //      (or same-instruction-read) bytes. No RAW hazard.
    float sq[2][8];
    #pragma unroll
    for (int t = 0; t < 2; t++) {
        mbar_wait(t ? mbar1 : mbar0, 0);
        char* sl = t ? slice1 : slice0;
        const float4* xt = reinterpret_cast<const float4*>(sl);
        #pragma unroll
        for (int i = 0; i < 8; i++) {
            const int ci = i * 32 + lane;
            float4 v = xt[ci];
            sq[t][i] = v.x * v.x + v.y * v.y + v.z * v.z + v.w * v.w;
            const int r     = ci >> 4;
            const int col4  = ci & 15;
            const int ch    = col4 >> 1;
            const int half8 = col4 & 1;
            const int rx    = (r & 7) ^ ((r & 8) >> 1);
            uint2 h;
            h.x = pack_f16x2(v.x, v.y);
            h.y = pack_f16x2(v.z, v.w);
            *reinterpret_cast<uint2*>(sl + r * 128 + ((ch ^ rx) * 16) + half8 * 8) = h;
        }
    }
    __syncwarp();

    // ---- A fragments via ldmatrix.x4 (both tiles).
    uint32_t ab[2][4][4];
    {
        const int row   = (lane & 7) + ((lane >> 3) & 1) * 8;
        const int chsel = (lane >> 4);
        const int rx    = (row & 7) ^ ((row & 8) >> 1);
        #pragma unroll
        for (int t = 0; t < 2; t++) {
            const uint32_t base = smem_u32((t ? slice1 : slice0) + row * 128);
            #pragma unroll
            for (int kb = 0; kb < 4; kb++) {
                const int phys = (2 * kb + chsel) ^ rx;
                ldsm_x4(ab[t][kb], base + phys * 16);
            }
        }
    }

    // ---- Deferred x2 reductions (exact fp32).
    #pragma unroll
    for (int t = 0; t < 2; t++) {
        #pragma unroll
        for (int i = 0; i < 8; i++) {
            sq[t][i] += __shfl_xor_sync(0xffffffffu, sq[t][i], 1);
            sq[t][i] += __shfl_xor_sync(0xffffffffu, sq[t][i], 2);
            sq[t][i] += __shfl_xor_sync(0xffffffffu, sq[t][i], 4);
            sq[t][i] += __shfl_xor_sync(0xffffffffu, sq[t][i], 8);
        }
    }
    if (lane == 0) {
        #pragma unroll
        for (int t = 0; t < 2; t++)
            #pragma unroll
            for (int i = 0; i < 8; i++) x2s[warp * 32 + 16 * t + 2 * i] = sq[t][i];
    } else if (lane == 16) {
        #pragma unroll
        for (int t = 0; t < 2; t++)
            #pragma unroll
            for (int i = 0; i < 8; i++) x2s[warp * 32 + 16 * t + 2 * i + 1] = sq[t][i];
    }

    // ---- GEMM: f16 accumulators, B fragments read ONCE per pair of m-tiles.
    uint32_t acc[2][8][2];   // [tile][nt][row-half], each u32 = f16x2
    #pragma unroll
    for (int nt = 0; nt < 8; nt++) {
        #pragma unroll
        for (int t = 0; t < 2; t++) { acc[t][nt][0] = 0u; acc[t][nt][1] = 0u; }
        uint4 bA = fragB4[nt * 2][lane];
        uint4 bB = fragB4[nt * 2 + 1][lane];
        #pragma unroll
        for (int t = 0; t < 2; t++) {
            mma_f16(acc[t][nt], ab[t][0][0], ab[t][0][1], ab[t][0][2], ab[t][0][3], bA.x, bA.y);
            mma_f16(acc[t][nt], ab[t][1][0], ab[t][1][1], ab[t][1][2], ab[t][1][3], bA.z, bA.w);
            mma_f16(acc[t][nt], ab[t][2][0], ab[t][2][1], ab[t][2][2], ab[t][2][3], bB.x, bB.y);
            mma_f16(acc[t][nt], ab[t][3][0], ab[t][3][1], ab[t][3][2], ab[t][3][3], bB.z, bB.w);
        }
    }
    __syncwarp();   // all slice reads (ldsm) done; slices reused as epi stages

    // ---- Epilogue per tile: stage 16 rows (swizzled) in own slice -> 8x STG.128.
    const int jj   = lane & 15;
    const int rhal = lane >> 4;
    #pragma unroll
    for (int t = 0; t < 2; t++) {
        float2* stage2 = reinterpret_cast<float2*>(t ? slice1 : slice0); // 16r x 32 f2
        const float p_lo = x2s[warp * 32 + 16 * t + g];
        const float p_hi = x2s[warp * 32 + 16 * t + g + 8];
        #pragma unroll
        for (int pass = 0; pass < 2; pass++) {
            const float p = pass ? p_hi : p_lo;
            const int rr = pass * 8 + g;
            #pragma unroll
            for (int nt = 0; nt < 8; nt++) {
                const int ucol = nt * 8 + t4 * 2;
                float2 w2v = *reinterpret_cast<const float2*>(&w2_s[ucol]);
                const __half2 h = *reinterpret_cast<const __half2*>(&acc[t][nt][pass]);
                const float2 f = __half22float2(h);
                float2 o;
                o.x = p + w2v.x - 2.f * f.x;
                o.y = p + w2v.y - 2.f * f.y;
                const int sidx = nt * 4 + t4;
                stage2[rr * 32 + (sidx ^ ((g & 3) * 4))] = o;
            }
        }
        __syncwarp();
        const long row0 = ctarow + t * CHUNK_ROWS + warp * 16;
        #pragma unroll
        for (int s8 = 0; s8 < 8; s8++) {
            const int r = s8 * 2 + rhal;
            const int phys = (2 * jj) ^ ((r & 3) * 4);
            float4 v = *reinterpret_cast<const float4*>(&stage2[r * 32 + phys]);
            const long grow = row0 + r;
            __stcs(reinterpret_cast<float4*>(out + grow * UNITS + jj * 4), v);
        }
    }
}

extern "C" void kernel_launch(void* const* d_in, const int* in_sizes, int n_in,
                              void* d_out, int out_size) {
    const float* x = (const float*)d_in[0];
    const float* w = (const float*)d_in[1];
    float* out = (float*)d_out;
    cudaFuncSetAttribute(sqdist_kernel,
                         cudaFuncAttributeMaxDynamicSharedMemorySize, SMEM_TOTAL);
    const int M = in_sizes[0] / DEPTH;   // 524288
    const int grid = M / 256;            // 2048
    sqdist_kernel<<<grid, 256, SMEM_TOTAL>>>(x, w, out);
}